// round 14
// baseline (speedup 1.0000x reference)
#include <cuda_runtime.h>
#include <math.h>

#define TPB     128
#define NGROUPS 4
#define GSIZE   32                // l-chunks per block
#define CHUNK   16                // l's per thread
#define NPACK   (CHUNK / 2)       // 8 packed f32x2 accumulators
#define LSPLIT  4                 // y-blocks per d

// ---- packed f32x2 helpers (PTX-only) ----
__device__ __forceinline__ unsigned long long pack2(float lo, float hi) {
    unsigned long long r;
    asm("mov.b64 %0, {%1, %2};" : "=l"(r) : "f"(lo), "f"(hi));
    return r;
}
__device__ __forceinline__ void unpack2(unsigned long long v, float& lo, float& hi) {
    asm("mov.b64 {%0, %1}, %2;" : "=f"(lo), "=f"(hi) : "l"(v));
}
__device__ __forceinline__ unsigned long long fma2(unsigned long long a,
                                                   unsigned long long b,
                                                   unsigned long long c) {
    unsigned long long d;
    asm("fma.rn.f32x2 %0, %1, %2, %3;" : "=l"(d) : "l"(a), "l"(b), "l"(c));
    return d;
}
__device__ __forceinline__ unsigned long long mul2(unsigned long long a,
                                                   unsigned long long b) {
    unsigned long long d;
    asm("mul.rn.f32x2 %0, %1, %2;" : "=l"(d) : "l"(a), "l"(b));
    return d;
}
__device__ __forceinline__ unsigned long long add2(unsigned long long a,
                                                   unsigned long long b) {
    unsigned long long d;
    asm("add.rn.f32x2 %0, %1, %2;" : "=l"(d) : "l"(a), "l"(b));
    return d;
}

// 3-term Cody-Waite reduction of x mod 2*pi (exact FMAs for q <= ~8K)
__device__ __forceinline__ float reduce_2pi(float x) {
    const float INV2PI = 0.15915494309189535f;
    const float C1 = 6.28125f;
    const float C2 = 0.0019350051879882812f;
    const float C3 = 3.0197e-7f;
    float q = rintf(x * INV2PI);
    float r = fmaf(q, -C1, x);
    r = fmaf(q, -C2, r);
    r = fmaf(q, -C3, r);
    return r;
}

__global__ void __launch_bounds__(TPB, 10)
lssl_hiocc_kernel(
    const float* __restrict__ Lre, const float* __restrict__ Lim,
    const float* __restrict__ Bre, const float* __restrict__ Bim,
    const float* __restrict__ Cre, const float* __restrict__ Cim,
    const float* __restrict__ Dp,  const float* __restrict__ logdt,
    float* __restrict__ out, int N, int L, int d_model)
{
    // dynamic smem: 4 x float4 (=64B) per n:
    //  [0] A  = (log|a|, arg a, log|w|, arg w)
    //  [1] B4 = (a.re, a.im, tr, det)
    //  [2] (tr2,tr2,det2,det2)
    //  [3] (tr4,tr4,det4,det4)
    extern __shared__ float4 S[];

    __shared__ unsigned long long bufA[GSIZE][NPACK + 1];
    __shared__ unsigned long long bufB[GSIZE][NPACK + 1];

    const int d = blockIdx.x;
    const int t = threadIdx.x;

    // ---- Phase 1: per-(d,n) constants ----
    for (int n = t; n < N; n += TPB) {
        const int idx = d * N + n;
        float lr = Lre[idx], li = Lim[idx];
        float sp = fmaxf(lr, 0.0f) + log1pf(expf(-fabsf(lr)));  // softplus
        float lam_re = -sp, lam_im = li;
        float dt = expf(logdt[d]);

        float hre = 0.5f * dt * lam_re;
        float him = 0.5f * dt * lam_im;
        float dre = 1.0f - hre;
        float dim = -him;
        float inv = 1.0f / (dre * dre + dim * dim);

        float nre = 1.0f + hre, nim = him;
        float are = (nre * dre + nim * dim) * inv;   // a_bar
        float aim = (nim * dre - nre * dim) * inv;

        float br = Bre[idx], bi = Bim[idx];
        float bbre = dt * inv * (br * dre + bi * dim);
        float bbim = dt * inv * (bi * dre - br * dim);
        float cr = Cre[idx], ci = Cim[idx];
        float wre = cr * bbre - ci * bbim;           // w = C*b_bar
        float wim = cr * bbim + ci * bbre;

        float mag2 = are * are + aim * aim;
        float tr  = are + are;                       // 2 Re(a)
        float det = -mag2;                           // -|a|^2
        float tr2  = fmaf(tr, tr, 2.0f * det);       // stride-2 coeffs
        float det2 = -det * det;
        float tr4  = fmaf(tr2, tr2, 2.0f * det2);    // stride-4 coeffs
        float det4 = -det2 * det2;

        float wmag2 = wre * wre + wim * wim;
        float4* p = S + (n << 2);
        p[0] = make_float4(0.5f * logf(mag2), atan2f(aim, are),
                           0.5f * logf(wmag2), atan2f(wim, wre));
        p[1] = make_float4(are, aim, tr, det);
        p[2] = make_float4(tr2, tr2, det2, det2);
        p[3] = make_float4(tr4, tr4, det4, det4);
    }

    if (blockIdx.y == 0 && t == 0) {
        out[(size_t)d_model * (size_t)L + d] = Dp[d];  // D passthrough
    }
    __syncthreads();

    // ---- Phase 2: NGROUPS n-groups over this block's l-range ----
    const int grp = t / GSIZE;
    const int tg  = t % GSIZE;
    const int l0  = (blockIdx.y * GSIZE + tg) * CHUNK;
    const int nper = N / NGROUPS;
    const int n_begin = grp * nper;
    const int n_end   = n_begin + nper;

    unsigned long long acc[NPACK];
#pragma unroll
    for (int m = 0; m < NPACK; m++) acc[m] = 0ull;

    if (l0 < L) {
        const float fl0 = (float)l0;

        for (int n = n_begin; n < n_end; n++) {
            const float4* p = S + (n << 2);
            const ulonglong2* pc = (const ulonglong2*)p;
            const float4 A  = p[0];
            const float4 B4 = p[1];
            const ulonglong2 c2 = pc[2];   // (tr2p, det2p)
            const ulonglong2 c4 = pc[3];   // (tr4p, det4p)

            // seed: q = w * a^{l0} via fused log-magnitude + phase
            float e  = __expf(fmaf(fl0, A.x, A.z));
            float ph = reduce_2pi(fl0 * A.y) + A.w;
            float sn, cs;
            __sincosf(ph, &sn, &cs);
            float qre = e * cs, qim = e * sn;

            float s0 = qre;
            float s1 = fmaf(qre, B4.x, -(qim * B4.y));
            float s2 = fmaf(B4.z, s1, B4.w * s0);
            float s3 = fmaf(B4.z, s2, B4.w * s1);

            unsigned long long u0 = pack2(s0, s1);
            unsigned long long u1 = pack2(s2, s3);
            unsigned long long u2 = fma2(c2.x, u1, mul2(c2.y, u0));
            unsigned long long u3 = fma2(c2.x, u2, mul2(c2.y, u1));

            acc[0] = add2(acc[0], u0);
            acc[1] = add2(acc[1], u1);
            acc[2] = add2(acc[2], u2);
            acc[3] = add2(acc[3], u3);

            // twin independent stride-4 chains (m = 2..3)
            unsigned long long v_next = fma2(c4.x, u2, mul2(c4.y, u0));
            unsigned long long w_next = fma2(c4.x, u3, mul2(c4.y, u1));
            acc[4] = add2(acc[4], v_next);
            acc[5] = add2(acc[5], w_next);

            unsigned long long v2 = fma2(c4.x, v_next, mul2(c4.y, u2));
            unsigned long long w2 = fma2(c4.x, w_next, mul2(c4.y, u3));
            acc[6] = add2(acc[6], v2);
            acc[7] = add2(acc[7], w2);
        }
    }

    // ---- 2-stage tree reduction: (g2->g0, g3->g1), then g1->g0 ----
    if (grp == 2) {
#pragma unroll
        for (int m = 0; m < NPACK; m++) bufA[tg][m] = acc[m];
    } else if (grp == 3) {
#pragma unroll
        for (int m = 0; m < NPACK; m++) bufB[tg][m] = acc[m];
    }
    __syncthreads();

    if (grp == 0) {
#pragma unroll
        for (int m = 0; m < NPACK; m++) acc[m] = add2(acc[m], bufA[tg][m]);
    } else if (grp == 1) {
#pragma unroll
        for (int m = 0; m < NPACK; m++) acc[m] = add2(acc[m], bufB[tg][m]);
    }
    __syncthreads();

    if (grp == 1) {
#pragma unroll
        for (int m = 0; m < NPACK; m++) bufA[tg][m] = acc[m];
    }
    __syncthreads();

    if (grp == 0 && l0 < L) {
#pragma unroll
        for (int m = 0; m < NPACK; m++) acc[m] = add2(acc[m], bufA[tg][m]);

        float* Kout = out + (size_t)d * (size_t)L + l0;
        if (l0 + CHUNK <= L) {
#pragma unroll
            for (int m = 0; m < NPACK; m++) {
                *reinterpret_cast<unsigned long long*>(Kout + 2 * m) = acc[m];
            }
        } else {
#pragma unroll
            for (int m = 0; m < NPACK; m++) {
                float lo, hi;
                unpack2(acc[m], lo, hi);
                if (l0 + 2 * m     < L) Kout[2 * m]     = lo;
                if (l0 + 2 * m + 1 < L) Kout[2 * m + 1] = hi;
            }
        }
    }
}

extern "C" void kernel_launch(void* const* d_in, const int* in_sizes, int n_in,
                              void* d_out, int out_size)
{
    const float* Lre   = (const float*)d_in[0];
    const float* Lim   = (const float*)d_in[1];
    const float* Bre   = (const float*)d_in[2];
    const float* Bim   = (const float*)d_in[3];
    const float* Cre   = (const float*)d_in[4];
    const float* Cim   = (const float*)d_in[5];
    const float* Dp    = (const float*)d_in[6];
    const float* logdt = (const float*)d_in[7];
    float* out = (float*)d_out;

    const int d_model = in_sizes[6];                 // 512
    const int N = in_sizes[0] / d_model;             // 64
    const int L = (out_size - d_model) / d_model;    // 2048

    static int attrs_set = 0;
    if (!attrs_set) {
        cudaFuncSetAttribute(lssl_hiocc_kernel,
                             cudaFuncAttributePreferredSharedMemoryCarveout, 100);
        attrs_set = 1;
    }

    const int per_block_l = GSIZE * CHUNK;           // 512
    const int gridy = (L + per_block_l - 1) / per_block_l;  // 4

    dim3 grid(d_model, gridy);
    size_t shm = (size_t)N * 4 * sizeof(float4);     // 64B per n = 4KB
    lssl_hiocc_kernel<<<grid, TPB, shm>>>(
        Lre, Lim, Bre, Bim, Cre, Cim, Dp, logdt, out, N, L, d_model);
}

// round 15
// speedup vs baseline: 1.1382x; 1.1382x over previous
#include <cuda_runtime.h>
#include <math.h>

#define TPB     128
#define NGROUPS 4
#define GSIZE   32                // l-chunks per block
#define CHUNK   32                // l's per thread
#define NPACK   (CHUNK / 2)       // 16 packed f32x2 accumulators
#define NPER    16                // n's per group (N=64 / NGROUPS)

// ---- packed f32x2 helpers (PTX-only) ----
__device__ __forceinline__ unsigned long long pack2(float lo, float hi) {
    unsigned long long r;
    asm("mov.b64 %0, {%1, %2};" : "=l"(r) : "f"(lo), "f"(hi));
    return r;
}
__device__ __forceinline__ void unpack2(unsigned long long v, float& lo, float& hi) {
    asm("mov.b64 {%0, %1}, %2;" : "=f"(lo), "=f"(hi) : "l"(v));
}
__device__ __forceinline__ unsigned long long fma2(unsigned long long a,
                                                   unsigned long long b,
                                                   unsigned long long c) {
    unsigned long long d;
    asm("fma.rn.f32x2 %0, %1, %2, %3;" : "=l"(d) : "l"(a), "l"(b), "l"(c));
    return d;
}
__device__ __forceinline__ unsigned long long mul2(unsigned long long a,
                                                   unsigned long long b) {
    unsigned long long d;
    asm("mul.rn.f32x2 %0, %1, %2;" : "=l"(d) : "l"(a), "l"(b));
    return d;
}
__device__ __forceinline__ unsigned long long add2(unsigned long long a,
                                                   unsigned long long b) {
    unsigned long long d;
    asm("add.rn.f32x2 %0, %1, %2;" : "=l"(d) : "l"(a), "l"(b));
    return d;
}

// 3-term Cody-Waite reduction of x mod 2*pi (exact FMAs for q <= ~8K)
__device__ __forceinline__ float reduce_2pi(float x) {
    const float INV2PI = 0.15915494309189535f;
    const float C1 = 6.28125f;
    const float C2 = 0.0019350051879882812f;
    const float C3 = 3.0197e-7f;
    float q = rintf(x * INV2PI);
    float r = fmaf(q, -C1, x);
    r = fmaf(q, -C2, r);
    r = fmaf(q, -C3, r);
    return r;
}

// one fully-inlined n-iteration of the hot loop
__device__ __forceinline__ void do_iter(
    const float4* __restrict__ p, float fl0, unsigned long long* acc)
{
    const ulonglong2* pc = (const ulonglong2*)p;
    const float4 A  = p[0];
    const float4 B4 = p[1];
    const ulonglong2 c2 = pc[2];   // (tr2p, det2p)
    const ulonglong2 c4 = pc[3];   // (tr4p, det4p)

    // seed: q = w * a^{l0} via fused log-magnitude + phase
    float e  = __expf(fmaf(fl0, A.x, A.z));
    float ph = reduce_2pi(fl0 * A.y) + A.w;
    float sn, cs;
    __sincosf(ph, &sn, &cs);
    float qre = e * cs, qim = e * sn;

    float s0 = qre;
    float s1 = fmaf(qre, B4.x, -(qim * B4.y));
    float s2 = fmaf(B4.z, s1, B4.w * s0);
    float s3 = fmaf(B4.z, s2, B4.w * s1);

    unsigned long long u0 = pack2(s0, s1);
    unsigned long long u1 = pack2(s2, s3);
    unsigned long long u2 = fma2(c2.x, u1, mul2(c2.y, u0));
    unsigned long long u3 = fma2(c2.x, u2, mul2(c2.y, u1));

    acc[0] = add2(acc[0], u0);
    acc[1] = add2(acc[1], u1);
    acc[2] = add2(acc[2], u2);
    acc[3] = add2(acc[3], u3);

    // twin independent stride-4 chains
    unsigned long long v_prev = u0, v_cur = u2;
    unsigned long long w_prev = u1, w_cur = u3;
#pragma unroll
    for (int m = 2; m < NPACK / 2; m++) {
        unsigned long long v_next = fma2(c4.x, v_cur, mul2(c4.y, v_prev));
        unsigned long long w_next = fma2(c4.x, w_cur, mul2(c4.y, w_prev));
        acc[2 * m]     = add2(acc[2 * m],     v_next);
        acc[2 * m + 1] = add2(acc[2 * m + 1], w_next);
        v_prev = v_cur; v_cur = v_next;
        w_prev = w_cur; w_cur = w_next;
    }
}

__global__ void __launch_bounds__(TPB, 7)
lssl_unroll_kernel(
    const float* __restrict__ Lre, const float* __restrict__ Lim,
    const float* __restrict__ Bre, const float* __restrict__ Bim,
    const float* __restrict__ Cre, const float* __restrict__ Cim,
    const float* __restrict__ Dp,  const float* __restrict__ logdt,
    float* __restrict__ out, int N, int L, int d_model)
{
    // dynamic smem: 4 x float4 (=64B) per n
    extern __shared__ float4 S[];

    __shared__ unsigned long long bufA[GSIZE][NPACK + 1];
    __shared__ unsigned long long bufB[GSIZE][NPACK + 1];

    const int d = blockIdx.x;
    const int t = threadIdx.x;

    // ---- Phase 1: per-(d,n) constants ----
    for (int n = t; n < N; n += TPB) {
        const int idx = d * N + n;
        float lr = Lre[idx], li = Lim[idx];
        float sp = fmaxf(lr, 0.0f) + log1pf(expf(-fabsf(lr)));  // softplus
        float lam_re = -sp, lam_im = li;
        float dt = expf(logdt[d]);

        float hre = 0.5f * dt * lam_re;
        float him = 0.5f * dt * lam_im;
        float dre = 1.0f - hre;
        float dim = -him;
        float inv = 1.0f / (dre * dre + dim * dim);

        float nre = 1.0f + hre, nim = him;
        float are = (nre * dre + nim * dim) * inv;   // a_bar
        float aim = (nim * dre - nre * dim) * inv;

        float br = Bre[idx], bi = Bim[idx];
        float bbre = dt * inv * (br * dre + bi * dim);
        float bbim = dt * inv * (bi * dre - br * dim);
        float cr = Cre[idx], ci = Cim[idx];
        float wre = cr * bbre - ci * bbim;           // w = C*b_bar
        float wim = cr * bbim + ci * bbre;

        float mag2 = are * are + aim * aim;
        float tr  = are + are;                       // 2 Re(a)
        float det = -mag2;                           // -|a|^2
        float tr2  = fmaf(tr, tr, 2.0f * det);       // stride-2 coeffs
        float det2 = -det * det;
        float tr4  = fmaf(tr2, tr2, 2.0f * det2);    // stride-4 coeffs
        float det4 = -det2 * det2;

        float wmag2 = wre * wre + wim * wim;
        float4* p = S + (n << 2);
        p[0] = make_float4(0.5f * logf(mag2), atan2f(aim, are),
                           0.5f * logf(wmag2), atan2f(wim, wre));
        p[1] = make_float4(are, aim, tr, det);
        p[2] = make_float4(tr2, tr2, det2, det2);
        p[3] = make_float4(tr4, tr4, det4, det4);
    }

    if (blockIdx.y == 0 && t == 0) {
        out[(size_t)d_model * (size_t)L + d] = Dp[d];  // D passthrough
    }
    __syncthreads();

    // ---- Phase 2: NGROUPS n-groups over this block's l-range ----
    const int grp = t / GSIZE;
    const int tg  = t % GSIZE;
    const int l0  = (blockIdx.y * GSIZE + tg) * CHUNK;
    const float fl0 = (float)l0;

    unsigned long long acc[NPACK];
#pragma unroll
    for (int m = 0; m < NPACK; m++) acc[m] = 0ull;

    if (N == 64) {
        // fully unrolled hot loop: 16 compile-time iterations
        const float4* base = S + ((grp * NPER) << 2);
#pragma unroll
        for (int k = 0; k < NPER; k++) {
            do_iter(base + (k << 2), fl0, acc);
        }
    } else {
        const int nper = N / NGROUPS;
        const float4* base = S + ((grp * nper) << 2);
        for (int k = 0; k < nper; k++) {
            do_iter(base + (k << 2), fl0, acc);
        }
    }

    // ---- 2-stage tree reduction: (g2->g0, g3->g1), then g1->g0 ----
    if (grp == 2) {
#pragma unroll
        for (int m = 0; m < NPACK; m++) bufA[tg][m] = acc[m];
    } else if (grp == 3) {
#pragma unroll
        for (int m = 0; m < NPACK; m++) bufB[tg][m] = acc[m];
    }
    __syncthreads();

    if (grp == 0) {
#pragma unroll
        for (int m = 0; m < NPACK; m++) acc[m] = add2(acc[m], bufA[tg][m]);
    } else if (grp == 1) {
#pragma unroll
        for (int m = 0; m < NPACK; m++) acc[m] = add2(acc[m], bufB[tg][m]);
    }
    __syncthreads();

    if (grp == 1) {
#pragma unroll
        for (int m = 0; m < NPACK; m++) bufA[tg][m] = acc[m];
    }
    __syncthreads();

    if (grp == 0) {
#pragma unroll
        for (int m = 0; m < NPACK; m++) acc[m] = add2(acc[m], bufA[tg][m]);

        float* Kout = out + (size_t)d * (size_t)L + l0;
        if (l0 + CHUNK <= L) {
#pragma unroll
            for (int m = 0; m < NPACK; m++) {
                *reinterpret_cast<unsigned long long*>(Kout + 2 * m) = acc[m];
            }
        } else {
#pragma unroll
            for (int m = 0; m < NPACK; m++) {
                float lo, hi;
                unpack2(acc[m], lo, hi);
                if (l0 + 2 * m     < L) Kout[2 * m]     = lo;
                if (l0 + 2 * m + 1 < L) Kout[2 * m + 1] = hi;
            }
        }
    }
}

extern "C" void kernel_launch(void* const* d_in, const int* in_sizes, int n_in,
                              void* d_out, int out_size)
{
    const float* Lre   = (const float*)d_in[0];
    const float* Lim   = (const float*)d_in[1];
    const float* Bre   = (const float*)d_in[2];
    const float* Bim   = (const float*)d_in[3];
    const float* Cre   = (const float*)d_in[4];
    const float* Cim   = (const float*)d_in[5];
    const float* Dp    = (const float*)d_in[6];
    const float* logdt = (const float*)d_in[7];
    float* out = (float*)d_out;

    const int d_model = in_sizes[6];                 // 512
    const int N = in_sizes[0] / d_model;             // 64
    const int L = (out_size - d_model) / d_model;    // 2048

    static int attrs_set = 0;
    if (!attrs_set) {
        cudaFuncSetAttribute(lssl_unroll_kernel,
                             cudaFuncAttributePreferredSharedMemoryCarveout, 100);
        attrs_set = 1;
    }

    const int per_block_l = GSIZE * CHUNK;           // 1024
    const int gridy = (L + per_block_l - 1) / per_block_l;  // 2

    dim3 grid(d_model, gridy);
    size_t shm = (size_t)N * 4 * sizeof(float4);     // 64B per n = 4KB
    lssl_unroll_kernel<<<grid, TPB, shm>>>(
        Lre, Lim, Bre, Bim, Cre, Cim, Dp, logdt, out, N, L, d_model);
}